// round 9
// baseline (speedup 1.0000x reference)
#include <cuda_runtime.h>
#include <cuda_bf16.h>
#include <stdint.h>

// Problem constants (fixed by the dataset)
#define MAXN 50000
#define MAXE 500000
#define DIN  128

// ---------------- scratch (device globals; no allocation allowed) ----------------
__device__ __align__(16) float g_Hs[(size_t)MAXN * 128];   // (X@W1)*dinv
__device__ __align__(16) float g_h1[(size_t)MAXN * 128];   // relu(layer1 out)
__device__ __align__(16) float g_Gs[(size_t)MAXN * 64];    // (h1@W2)*dinv
__device__ int   g_cnt[MAXN];                // in-degree (no self loop)
__device__ int   g_fill[MAXN];               // bucket fill cursors
__device__ int   g_rowptr[MAXN + 1];         // CSR row pointers (by dst)
__device__ int   g_srcs[MAXE];               // CSR column (src) indices
__device__ float g_dinv[MAXN];               // 1/sqrt(deg), deg = indeg+1
__device__ int   g_bsum[128];                // scan block sums
__device__ int   g_boff[128];                // scan block offsets

// ---------------- preprocessing ----------------
__global__ void k_init(int n) {
    int i = blockIdx.x * blockDim.x + threadIdx.x;
    if (i < n) { g_cnt[i] = 0; g_fill[i] = 0; }
}

// edge_index is int32 (JAX x64 disabled)
__global__ void k_count(const int* __restrict__ ei, int E, int n) {
    int e = blockIdx.x * blockDim.x + threadIdx.x;
    if (e < E) {
        int d = ei[E + e];
        if ((unsigned)d < (unsigned)n)
            atomicAdd(&g_cnt[d], 1);
    }
}

// exclusive scan, 512 elements per block
__global__ void k_scan1(int n) {
    __shared__ int sh[512];
    int i = blockIdx.x * 512 + threadIdx.x;
    int v = (i < n) ? g_cnt[i] : 0;
    sh[threadIdx.x] = v;
    __syncthreads();
    for (int off = 1; off < 512; off <<= 1) {
        int t = 0;
        if ((int)threadIdx.x >= off) t = sh[threadIdx.x - off];
        __syncthreads();
        sh[threadIdx.x] += t;
        __syncthreads();
    }
    int incl = sh[threadIdx.x];
    if (i < n) g_rowptr[i] = incl - v;       // block-local exclusive
    if (threadIdx.x == 511) g_bsum[blockIdx.x] = incl;
}

// parallel scan of <=128 block sums (was: 1-thread serial chain, 8.5us)
__global__ void k_scan2(int nb) {
    __shared__ int sh[128];
    int t = threadIdx.x;
    int v = (t < nb) ? g_bsum[t] : 0;
    sh[t] = v;
    __syncthreads();
    for (int off = 1; off < 128; off <<= 1) {
        int p = 0;
        if (t >= off) p = sh[t - off];
        __syncthreads();
        sh[t] += p;
        __syncthreads();
    }
    if (t < nb) g_boff[t] = sh[t] - v;       // exclusive
}

__global__ void k_scan3(int n) {
    int i = blockIdx.x * blockDim.x + threadIdx.x;
    if (i < n) {
        int rp = g_rowptr[i] + g_boff[i >> 9];
        g_rowptr[i] = rp;
        g_dinv[i] = rsqrtf((float)(g_cnt[i] + 1));
        if (i == n - 1) g_rowptr[n] = rp + g_cnt[i];
    }
}

__global__ void k_fill(const int* __restrict__ ei, int E, int n) {
    int e = blockIdx.x * blockDim.x + threadIdx.x;
    if (e < E) {
        int s = ei[e];
        int d = ei[E + e];
        if ((unsigned)s < (unsigned)n && (unsigned)d < (unsigned)n) {
            int pos = g_rowptr[d] + atomicAdd(&g_fill[d], 1);
            g_srcs[pos] = s;
        }
    }
}

// ---------------- GEMM: out[node][f] = (sum_k in[node][k] * W[k][f]) * dinv[node] ----------------
// X tile stored TRANSPOSED in smem: sX[k][node_local] -> one LDS.128 fetches the
// 4 x-values a thread needs per k (was 4 scalar LDS). 3 LDS.128 per 32 FFMA.
template <int F, int LAYER>
__global__ void k_gemm(const float* __restrict__ Xin, const float* __restrict__ W, int n) {
    constexpr int CG  = F / 8;          // column groups (8 cols each)
    constexpr int NG  = 256 / CG;       // node groups (4 nodes each)
    constexpr int NB  = NG * 4;         // nodes per block (64 or 128)
    constexpr int KC  = 32;             // k-chunk
    constexpr int NBP = NB + 4;         // padded row (16B-aligned stride)

    __shared__ __align__(16) float sW[KC][F];
    __shared__ __align__(16) float sX[KC][NBP];

    const float* __restrict__ in;
    float* __restrict__ out;
    if (LAYER == 1) { in = Xin;   out = g_Hs; }
    else            { in = g_h1;  out = g_Gs; }

    const int tid = threadIdx.x;
    const int cg  = tid % CG;
    const int ng  = tid / CG;
    const int node0 = blockIdx.x * NB;

    float acc[4][8];
    #pragma unroll
    for (int a = 0; a < 4; a++)
        #pragma unroll
        for (int b = 0; b < 8; b++) acc[a][b] = 0.f;

    for (int k0 = 0; k0 < DIN; k0 += KC) {
        // load W chunk (rows k0..k0+KC-1 contiguous in gmem)
        {
            const float4* wsrc = (const float4*)(W + (size_t)k0 * F);
            float4* wdst = (float4*)&sW[0][0];
            #pragma unroll
            for (int i = tid; i < KC * F / 4; i += 256) wdst[i] = wsrc[i];
        }
        // load X chunk, store transposed: sX[k][r]
        #pragma unroll
        for (int i = tid; i < NB * KC / 4; i += 256) {
            int r = i / (KC / 4);
            int c = i % (KC / 4);
            int node = node0 + r;
            float4 v = make_float4(0.f, 0.f, 0.f, 0.f);
            if (node < n) v = *(const float4*)(in + (size_t)node * DIN + k0 + c * 4);
            sX[c * 4 + 0][r] = v.x;
            sX[c * 4 + 1][r] = v.y;
            sX[c * 4 + 2][r] = v.z;
            sX[c * 4 + 3][r] = v.w;
        }
        __syncthreads();

        #pragma unroll
        for (int k = 0; k < KC; k++) {
            const float4 wa = *(const float4*)&sW[k][cg * 8];
            const float4 wb = *(const float4*)&sW[k][cg * 8 + 4];
            const float4 xv = *(const float4*)&sX[k][ng * 4];
            acc[0][0] += xv.x * wa.x; acc[0][1] += xv.x * wa.y;
            acc[0][2] += xv.x * wa.z; acc[0][3] += xv.x * wa.w;
            acc[0][4] += xv.x * wb.x; acc[0][5] += xv.x * wb.y;
            acc[0][6] += xv.x * wb.z; acc[0][7] += xv.x * wb.w;
            acc[1][0] += xv.y * wa.x; acc[1][1] += xv.y * wa.y;
            acc[1][2] += xv.y * wa.z; acc[1][3] += xv.y * wa.w;
            acc[1][4] += xv.y * wb.x; acc[1][5] += xv.y * wb.y;
            acc[1][6] += xv.y * wb.z; acc[1][7] += xv.y * wb.w;
            acc[2][0] += xv.z * wa.x; acc[2][1] += xv.z * wa.y;
            acc[2][2] += xv.z * wa.z; acc[2][3] += xv.z * wa.w;
            acc[2][4] += xv.z * wb.x; acc[2][5] += xv.z * wb.y;
            acc[2][6] += xv.z * wb.z; acc[2][7] += xv.z * wb.w;
            acc[3][0] += xv.w * wa.x; acc[3][1] += xv.w * wa.y;
            acc[3][2] += xv.w * wa.z; acc[3][3] += xv.w * wa.w;
            acc[3][4] += xv.w * wb.x; acc[3][5] += xv.w * wb.y;
            acc[3][6] += xv.w * wb.z; acc[3][7] += xv.w * wb.w;
        }
        __syncthreads();
    }

    #pragma unroll
    for (int ni = 0; ni < 4; ni++) {
        int node = node0 + ng * 4 + ni;
        if (node < n) {
            float dv = g_dinv[node];
            float* o = out + (size_t)node * F + cg * 8;
            float4 o0 = make_float4(acc[ni][0] * dv, acc[ni][1] * dv, acc[ni][2] * dv, acc[ni][3] * dv);
            float4 o1 = make_float4(acc[ni][4] * dv, acc[ni][5] * dv, acc[ni][6] * dv, acc[ni][7] * dv);
            *(float4*)(o) = o0;
            *(float4*)(o + 4) = o1;
        }
    }
}

// ---------------- aggregation layer 1: h1 = relu(dinv*(gather + self) + b1) ----------------
// one warp per node, 32 lanes x float4 = 512B row
__global__ void k_agg1(const float* __restrict__ bias, int n) {
    const int w = (blockIdx.x * blockDim.x + threadIdx.x) >> 5;
    const int lane = threadIdx.x & 31;
    if (w >= n) return;

    const int beg = g_rowptr[w];
    const int end = g_rowptr[w + 1];
    const float dv = g_dinv[w];

    const float4* __restrict__ H4 = (const float4*)g_Hs;
    float4 a = H4[(size_t)w * 32 + lane];   // self-loop term
    int e = beg;
    for (; e + 3 < end; e += 4) {
        int s0 = g_srcs[e], s1 = g_srcs[e + 1], s2 = g_srcs[e + 2], s3 = g_srcs[e + 3];
        float4 v0 = H4[(size_t)s0 * 32 + lane];
        float4 v1 = H4[(size_t)s1 * 32 + lane];
        float4 v2 = H4[(size_t)s2 * 32 + lane];
        float4 v3 = H4[(size_t)s3 * 32 + lane];
        a.x += v0.x + v1.x + v2.x + v3.x;
        a.y += v0.y + v1.y + v2.y + v3.y;
        a.z += v0.z + v1.z + v2.z + v3.z;
        a.w += v0.w + v1.w + v2.w + v3.w;
    }
    for (; e < end; e++) {
        int s = g_srcs[e];
        float4 v = H4[(size_t)s * 32 + lane];
        a.x += v.x; a.y += v.y; a.z += v.z; a.w += v.w;
    }
    float4 bb = ((const float4*)bias)[lane];
    float4 o;
    o.x = fmaxf(a.x * dv + bb.x, 0.f);
    o.y = fmaxf(a.y * dv + bb.y, 0.f);
    o.z = fmaxf(a.z * dv + bb.z, 0.f);
    o.w = fmaxf(a.w * dv + bb.w, 0.f);
    ((float4*)g_h1)[(size_t)w * 32 + lane] = o;
}

// ---------------- aggregation layer 2: out = dinv*(gather + self) + b2 ----------------
// HALF-warp per node: 16 lanes x float4 = 64-float row. 2 nodes/warp -> 2x issue parallelism.
__global__ void k_agg2(const float* __restrict__ bias, float* __restrict__ Yout, int n) {
    const int hw = (blockIdx.x * blockDim.x + threadIdx.x) >> 4;  // half-warp id = node
    const int l  = threadIdx.x & 15;
    if (hw >= n) return;

    const int beg = g_rowptr[hw];
    const int end = g_rowptr[hw + 1];
    const float dv = g_dinv[hw];

    const float4* __restrict__ G4 = (const float4*)g_Gs;
    float4 a = G4[(size_t)hw * 16 + l];   // self-loop term
    int e = beg;
    for (; e + 3 < end; e += 4) {
        int s0 = g_srcs[e], s1 = g_srcs[e + 1], s2 = g_srcs[e + 2], s3 = g_srcs[e + 3];
        float4 v0 = G4[(size_t)s0 * 16 + l];
        float4 v1 = G4[(size_t)s1 * 16 + l];
        float4 v2 = G4[(size_t)s2 * 16 + l];
        float4 v3 = G4[(size_t)s3 * 16 + l];
        a.x += v0.x + v1.x + v2.x + v3.x;
        a.y += v0.y + v1.y + v2.y + v3.y;
        a.z += v0.z + v1.z + v2.z + v3.z;
        a.w += v0.w + v1.w + v2.w + v3.w;
    }
    for (; e < end; e++) {
        int s = g_srcs[e];
        float4 v = G4[(size_t)s * 16 + l];
        a.x += v.x; a.y += v.y; a.z += v.z; a.w += v.w;
    }
    float4 bb = ((const float4*)bias)[l];
    float4 o;
    o.x = a.x * dv + bb.x;
    o.y = a.y * dv + bb.y;
    o.z = a.z * dv + bb.z;
    o.w = a.w * dv + bb.w;
    ((float4*)Yout)[(size_t)hw * 16 + l] = o;
}

// ---------------- launch ----------------
extern "C" void kernel_launch(void* const* d_in, const int* in_sizes, int n_in,
                              void* d_out, int out_size) {
    const float* x  = (const float*)d_in[0];
    const int*   ei = (const int*)d_in[1];    // int32 (JAX x64 disabled)
    const float* W1 = (const float*)d_in[2];
    const float* b1 = (const float*)d_in[3];
    const float* W2 = (const float*)d_in[4];
    const float* b2 = (const float*)d_in[5];
    float*       out = (float*)d_out;

    const int n = in_sizes[0] / 128;   // 50000
    const int E = in_sizes[1] / 2;     // 500000
    const int nb = (n + 511) / 512;    // 98 <= 128

    k_init<<<(n + 255) / 256, 256>>>(n);
    k_count<<<(E + 255) / 256, 256>>>(ei, E, n);
    k_scan1<<<nb, 512>>>(n);
    k_scan2<<<1, 128>>>(nb);
    k_scan3<<<(n + 255) / 256, 256>>>(n);
    k_fill<<<(E + 255) / 256, 256>>>(ei, E, n);

    // layer 1: Hs = (x@W1)*dinv ; h1 = relu(dinv*(gather + self) + b1)
    k_gemm<128, 1><<<(n + 63) / 64, 256>>>(x, W1, n);
    k_agg1<<<(n + 7) / 8, 256>>>(b1, n);

    // layer 2: Gs = (h1@W2)*dinv ; out = dinv*(gather + self) + b2
    k_gemm<64, 2><<<(n + 127) / 128, 256>>>(nullptr, W2, n);
    k_agg2<<<(n + 15) / 16, 256>>>(b2, out, n);
}

// round 10
// speedup vs baseline: 1.0011x; 1.0011x over previous
#include <cuda_runtime.h>
#include <cuda_bf16.h>
#include <stdint.h>

// Problem constants (fixed by the dataset)
#define MAXN 50000
#define MAXE 500000
#define DIN  128

// ---------------- scratch (device globals; no allocation allowed) ----------------
__device__ __align__(16) float g_Hs[(size_t)MAXN * 128];   // (X@W1)*dinv
__device__ __align__(16) float g_h1[(size_t)MAXN * 128];   // relu(layer1 out)
__device__ __align__(16) float g_Gs[(size_t)MAXN * 64];    // (h1@W2)*dinv
__device__ int   g_cnt[MAXN];                // in-degree (no self loop)
__device__ int   g_fill[MAXN];               // bucket fill cursors
__device__ int   g_rowptr[MAXN + 1];         // CSR row pointers (by dst)
__device__ int   g_srcs[MAXE];               // CSR column (src) indices
__device__ float g_dinv[MAXN];               // 1/sqrt(deg), deg = indeg+1
__device__ int   g_bsum[128];                // scan block sums
__device__ int   g_boff[128];                // scan block offsets

// ---------------- preprocessing ----------------
__global__ void k_init(int n) {
    int i = blockIdx.x * blockDim.x + threadIdx.x;
    if (i < n) { g_cnt[i] = 0; g_fill[i] = 0; }
}

// edge_index is int32 (JAX x64 disabled)
__global__ void k_count(const int* __restrict__ ei, int E, int n) {
    int e = blockIdx.x * blockDim.x + threadIdx.x;
    if (e < E) {
        int d = ei[E + e];
        if ((unsigned)d < (unsigned)n)
            atomicAdd(&g_cnt[d], 1);
    }
}

// exclusive scan, 512 elements per block
__global__ void k_scan1(int n) {
    __shared__ int sh[512];
    int i = blockIdx.x * 512 + threadIdx.x;
    int v = (i < n) ? g_cnt[i] : 0;
    sh[threadIdx.x] = v;
    __syncthreads();
    for (int off = 1; off < 512; off <<= 1) {
        int t = 0;
        if ((int)threadIdx.x >= off) t = sh[threadIdx.x - off];
        __syncthreads();
        sh[threadIdx.x] += t;
        __syncthreads();
    }
    int incl = sh[threadIdx.x];
    if (i < n) g_rowptr[i] = incl - v;       // block-local exclusive
    if (threadIdx.x == 511) g_bsum[blockIdx.x] = incl;
}

// parallel scan of <=128 block sums (was: 1-thread serial chain, 8.5us)
__global__ void k_scan2(int nb) {
    __shared__ int sh[128];
    int t = threadIdx.x;
    int v = (t < nb) ? g_bsum[t] : 0;
    sh[t] = v;
    __syncthreads();
    for (int off = 1; off < 128; off <<= 1) {
        int p = 0;
        if (t >= off) p = sh[t - off];
        __syncthreads();
        sh[t] += p;
        __syncthreads();
    }
    if (t < nb) g_boff[t] = sh[t] - v;       // exclusive
}

__global__ void k_scan3(int n) {
    int i = blockIdx.x * blockDim.x + threadIdx.x;
    if (i < n) {
        int rp = g_rowptr[i] + g_boff[i >> 9];
        g_rowptr[i] = rp;
        g_dinv[i] = rsqrtf((float)(g_cnt[i] + 1));
        if (i == n - 1) g_rowptr[n] = rp + g_cnt[i];
    }
}

__global__ void k_fill(const int* __restrict__ ei, int E, int n) {
    int e = blockIdx.x * blockDim.x + threadIdx.x;
    if (e < E) {
        int s = ei[e];
        int d = ei[E + e];
        if ((unsigned)s < (unsigned)n && (unsigned)d < (unsigned)n) {
            int pos = g_rowptr[d] + atomicAdd(&g_fill[d], 1);
            g_srcs[pos] = s;
        }
    }
}

// ---------------- GEMM: out[node][f] = (sum_k in[node][k] * W[k][f]) * dinv[node] ----------------
// X tile stored TRANSPOSED in smem: sX[k][node_local] -> one LDS.128 fetches the
// 4 x-values a thread needs per k (was 4 scalar LDS). 3 LDS.128 per 32 FFMA.
template <int F, int LAYER>
__global__ void k_gemm(const float* __restrict__ Xin, const float* __restrict__ W, int n) {
    constexpr int CG  = F / 8;          // column groups (8 cols each)
    constexpr int NG  = 256 / CG;       // node groups (4 nodes each)
    constexpr int NB  = NG * 4;         // nodes per block (64 or 128)
    constexpr int KC  = 32;             // k-chunk
    constexpr int NBP = NB + 4;         // padded row (16B-aligned stride)

    __shared__ __align__(16) float sW[KC][F];
    __shared__ __align__(16) float sX[KC][NBP];

    const float* __restrict__ in;
    float* __restrict__ out;
    if (LAYER == 1) { in = Xin;   out = g_Hs; }
    else            { in = g_h1;  out = g_Gs; }

    const int tid = threadIdx.x;
    const int cg  = tid % CG;
    const int ng  = tid / CG;
    const int node0 = blockIdx.x * NB;

    float acc[4][8];
    #pragma unroll
    for (int a = 0; a < 4; a++)
        #pragma unroll
        for (int b = 0; b < 8; b++) acc[a][b] = 0.f;

    for (int k0 = 0; k0 < DIN; k0 += KC) {
        // load W chunk (rows k0..k0+KC-1 contiguous in gmem)
        {
            const float4* wsrc = (const float4*)(W + (size_t)k0 * F);
            float4* wdst = (float4*)&sW[0][0];
            #pragma unroll
            for (int i = tid; i < KC * F / 4; i += 256) wdst[i] = wsrc[i];
        }
        // load X chunk, store transposed: sX[k][r]
        #pragma unroll
        for (int i = tid; i < NB * KC / 4; i += 256) {
            int r = i / (KC / 4);
            int c = i % (KC / 4);
            int node = node0 + r;
            float4 v = make_float4(0.f, 0.f, 0.f, 0.f);
            if (node < n) v = *(const float4*)(in + (size_t)node * DIN + k0 + c * 4);
            sX[c * 4 + 0][r] = v.x;
            sX[c * 4 + 1][r] = v.y;
            sX[c * 4 + 2][r] = v.z;
            sX[c * 4 + 3][r] = v.w;
        }
        __syncthreads();

        #pragma unroll
        for (int k = 0; k < KC; k++) {
            const float4 wa = *(const float4*)&sW[k][cg * 8];
            const float4 wb = *(const float4*)&sW[k][cg * 8 + 4];
            const float4 xv = *(const float4*)&sX[k][ng * 4];
            acc[0][0] += xv.x * wa.x; acc[0][1] += xv.x * wa.y;
            acc[0][2] += xv.x * wa.z; acc[0][3] += xv.x * wa.w;
            acc[0][4] += xv.x * wb.x; acc[0][5] += xv.x * wb.y;
            acc[0][6] += xv.x * wb.z; acc[0][7] += xv.x * wb.w;
            acc[1][0] += xv.y * wa.x; acc[1][1] += xv.y * wa.y;
            acc[1][2] += xv.y * wa.z; acc[1][3] += xv.y * wa.w;
            acc[1][4] += xv.y * wb.x; acc[1][5] += xv.y * wb.y;
            acc[1][6] += xv.y * wb.z; acc[1][7] += xv.y * wb.w;
            acc[2][0] += xv.z * wa.x; acc[2][1] += xv.z * wa.y;
            acc[2][2] += xv.z * wa.z; acc[2][3] += xv.z * wa.w;
            acc[2][4] += xv.z * wb.x; acc[2][5] += xv.z * wb.y;
            acc[2][6] += xv.z * wb.z; acc[2][7] += xv.z * wb.w;
            acc[3][0] += xv.w * wa.x; acc[3][1] += xv.w * wa.y;
            acc[3][2] += xv.w * wa.z; acc[3][3] += xv.w * wa.w;
            acc[3][4] += xv.w * wb.x; acc[3][5] += xv.w * wb.y;
            acc[3][6] += xv.w * wb.z; acc[3][7] += xv.w * wb.w;
        }
        __syncthreads();
    }

    #pragma unroll
    for (int ni = 0; ni < 4; ni++) {
        int node = node0 + ng * 4 + ni;
        if (node < n) {
            float dv = g_dinv[node];
            float* o = out + (size_t)node * F + cg * 8;
            float4 o0 = make_float4(acc[ni][0] * dv, acc[ni][1] * dv, acc[ni][2] * dv, acc[ni][3] * dv);
            float4 o1 = make_float4(acc[ni][4] * dv, acc[ni][5] * dv, acc[ni][6] * dv, acc[ni][7] * dv);
            *(float4*)(o) = o0;
            *(float4*)(o + 4) = o1;
        }
    }
}

// ---------------- aggregation layer 1: h1 = relu(dinv*(gather + self) + b1) ----------------
// one warp per node, 32 lanes x float4 = 512B row
__global__ void k_agg1(const float* __restrict__ bias, int n) {
    const int w = (blockIdx.x * blockDim.x + threadIdx.x) >> 5;
    const int lane = threadIdx.x & 31;
    if (w >= n) return;

    const int beg = g_rowptr[w];
    const int end = g_rowptr[w + 1];
    const float dv = g_dinv[w];

    const float4* __restrict__ H4 = (const float4*)g_Hs;
    float4 a = H4[(size_t)w * 32 + lane];   // self-loop term
    int e = beg;
    for (; e + 3 < end; e += 4) {
        int s0 = g_srcs[e], s1 = g_srcs[e + 1], s2 = g_srcs[e + 2], s3 = g_srcs[e + 3];
        float4 v0 = H4[(size_t)s0 * 32 + lane];
        float4 v1 = H4[(size_t)s1 * 32 + lane];
        float4 v2 = H4[(size_t)s2 * 32 + lane];
        float4 v3 = H4[(size_t)s3 * 32 + lane];
        a.x += v0.x + v1.x + v2.x + v3.x;
        a.y += v0.y + v1.y + v2.y + v3.y;
        a.z += v0.z + v1.z + v2.z + v3.z;
        a.w += v0.w + v1.w + v2.w + v3.w;
    }
    for (; e < end; e++) {
        int s = g_srcs[e];
        float4 v = H4[(size_t)s * 32 + lane];
        a.x += v.x; a.y += v.y; a.z += v.z; a.w += v.w;
    }
    float4 bb = ((const float4*)bias)[lane];
    float4 o;
    o.x = fmaxf(a.x * dv + bb.x, 0.f);
    o.y = fmaxf(a.y * dv + bb.y, 0.f);
    o.z = fmaxf(a.z * dv + bb.z, 0.f);
    o.w = fmaxf(a.w * dv + bb.w, 0.f);
    ((float4*)g_h1)[(size_t)w * 32 + lane] = o;
}

// ---------------- aggregation layer 2: out = dinv*(gather + self) + b2 ----------------
// HALF-warp per node: 16 lanes x float4 = 64-float row. 2 nodes/warp -> 2x issue parallelism.
__global__ void k_agg2(const float* __restrict__ bias, float* __restrict__ Yout, int n) {
    const int hw = (blockIdx.x * blockDim.x + threadIdx.x) >> 4;  // half-warp id = node
    const int l  = threadIdx.x & 15;
    if (hw >= n) return;

    const int beg = g_rowptr[hw];
    const int end = g_rowptr[hw + 1];
    const float dv = g_dinv[hw];

    const float4* __restrict__ G4 = (const float4*)g_Gs;
    float4 a = G4[(size_t)hw * 16 + l];   // self-loop term
    int e = beg;
    for (; e + 3 < end; e += 4) {
        int s0 = g_srcs[e], s1 = g_srcs[e + 1], s2 = g_srcs[e + 2], s3 = g_srcs[e + 3];
        float4 v0 = G4[(size_t)s0 * 16 + l];
        float4 v1 = G4[(size_t)s1 * 16 + l];
        float4 v2 = G4[(size_t)s2 * 16 + l];
        float4 v3 = G4[(size_t)s3 * 16 + l];
        a.x += v0.x + v1.x + v2.x + v3.x;
        a.y += v0.y + v1.y + v2.y + v3.y;
        a.z += v0.z + v1.z + v2.z + v3.z;
        a.w += v0.w + v1.w + v2.w + v3.w;
    }
    for (; e < end; e++) {
        int s = g_srcs[e];
        float4 v = G4[(size_t)s * 16 + l];
        a.x += v.x; a.y += v.y; a.z += v.z; a.w += v.w;
    }
    float4 bb = ((const float4*)bias)[l];
    float4 o;
    o.x = a.x * dv + bb.x;
    o.y = a.y * dv + bb.y;
    o.z = a.z * dv + bb.z;
    o.w = a.w * dv + bb.w;
    ((float4*)Yout)[(size_t)hw * 16 + l] = o;
}

// ---------------- launch ----------------
extern "C" void kernel_launch(void* const* d_in, const int* in_sizes, int n_in,
                              void* d_out, int out_size) {
    const float* x  = (const float*)d_in[0];
    const int*   ei = (const int*)d_in[1];    // int32 (JAX x64 disabled)
    const float* W1 = (const float*)d_in[2];
    const float* b1 = (const float*)d_in[3];
    const float* W2 = (const float*)d_in[4];
    const float* b2 = (const float*)d_in[5];
    float*       out = (float*)d_out;

    const int n = in_sizes[0] / 128;   // 50000
    const int E = in_sizes[1] / 2;     // 500000
    const int nb = (n + 511) / 512;    // 98 <= 128

    k_init<<<(n + 255) / 256, 256>>>(n);
    k_count<<<(E + 255) / 256, 256>>>(ei, E, n);
    k_scan1<<<nb, 512>>>(n);
    k_scan2<<<1, 128>>>(nb);
    k_scan3<<<(n + 255) / 256, 256>>>(n);
    k_fill<<<(E + 255) / 256, 256>>>(ei, E, n);

    // layer 1: Hs = (x@W1)*dinv ; h1 = relu(dinv*(gather + self) + b1)
    k_gemm<128, 1><<<(n + 63) / 64, 256>>>(x, W1, n);
    k_agg1<<<(n + 7) / 8, 256>>>(b1, n);

    // layer 2: Gs = (h1@W2)*dinv ; out = dinv*(gather + self) + b2
    k_gemm<64, 2><<<(n + 127) / 128, 256>>>(nullptr, W2, n);
    k_agg2<<<(n + 15) / 16, 256>>>(b2, out, n);
}

// round 11
// speedup vs baseline: 1.0013x; 1.0002x over previous
#include <cuda_runtime.h>
#include <cuda_bf16.h>
#include <stdint.h>

// Problem constants (fixed by the dataset)
#define MAXN 50000
#define MAXE 500000
#define DIN  128

// ---------------- scratch (device globals; no allocation allowed) ----------------
__device__ __align__(16) float g_Hs[(size_t)MAXN * 128];   // (X@W1)*dinv
__device__ __align__(16) float g_h1[(size_t)MAXN * 128];   // relu(layer1 out)
__device__ __align__(16) float g_Gs[(size_t)MAXN * 64];    // (h1@W2)*dinv
__device__ int   g_cnt[MAXN];                // in-degree (no self loop)
__device__ int   g_fill[MAXN];               // bucket fill cursors
__device__ int   g_rowptr[MAXN + 1];         // CSR row pointers (by dst)
__device__ int   g_srcs[MAXE];               // CSR column (src) indices
__device__ float g_dinv[MAXN];               // 1/sqrt(deg), deg = indeg+1
__device__ int   g_bsum[128];                // scan block sums
__device__ int   g_boff[128];                // scan block offsets

// ---------------- preprocessing ----------------
__global__ void k_init(int n) {
    int i = blockIdx.x * blockDim.x + threadIdx.x;
    if (i < n) { g_cnt[i] = 0; g_fill[i] = 0; }
}

// edge_index is int32 (JAX x64 disabled)
__global__ void k_count(const int* __restrict__ ei, int E, int n) {
    int e = blockIdx.x * blockDim.x + threadIdx.x;
    if (e < E) {
        int d = ei[E + e];
        if ((unsigned)d < (unsigned)n)
            atomicAdd(&g_cnt[d], 1);
    }
}

// exclusive scan, 512 elements per block
__global__ void k_scan1(int n) {
    __shared__ int sh[512];
    int i = blockIdx.x * 512 + threadIdx.x;
    int v = (i < n) ? g_cnt[i] : 0;
    sh[threadIdx.x] = v;
    __syncthreads();
    for (int off = 1; off < 512; off <<= 1) {
        int t = 0;
        if ((int)threadIdx.x >= off) t = sh[threadIdx.x - off];
        __syncthreads();
        sh[threadIdx.x] += t;
        __syncthreads();
    }
    int incl = sh[threadIdx.x];
    if (i < n) g_rowptr[i] = incl - v;       // block-local exclusive
    if (threadIdx.x == 511) g_bsum[blockIdx.x] = incl;
}

// parallel scan of <=128 block sums (was: 1-thread serial chain, 8.5us)
__global__ void k_scan2(int nb) {
    __shared__ int sh[128];
    int t = threadIdx.x;
    int v = (t < nb) ? g_bsum[t] : 0;
    sh[t] = v;
    __syncthreads();
    for (int off = 1; off < 128; off <<= 1) {
        int p = 0;
        if (t >= off) p = sh[t - off];
        __syncthreads();
        sh[t] += p;
        __syncthreads();
    }
    if (t < nb) g_boff[t] = sh[t] - v;       // exclusive
}

__global__ void k_scan3(int n) {
    int i = blockIdx.x * blockDim.x + threadIdx.x;
    if (i < n) {
        int rp = g_rowptr[i] + g_boff[i >> 9];
        g_rowptr[i] = rp;
        g_dinv[i] = rsqrtf((float)(g_cnt[i] + 1));
        if (i == n - 1) g_rowptr[n] = rp + g_cnt[i];
    }
}

__global__ void k_fill(const int* __restrict__ ei, int E, int n) {
    int e = blockIdx.x * blockDim.x + threadIdx.x;
    if (e < E) {
        int s = ei[e];
        int d = ei[E + e];
        if ((unsigned)s < (unsigned)n && (unsigned)d < (unsigned)n) {
            int pos = g_rowptr[d] + atomicAdd(&g_fill[d], 1);
            g_srcs[pos] = s;
        }
    }
}

// ---------------- GEMM: out[node][f] = (sum_k in[node][k] * W[k][f]) * dinv[node] ----------------
// X tile stored TRANSPOSED in smem: sX[k][node_local] -> one LDS.128 fetches the
// 4 x-values a thread needs per k (was 4 scalar LDS). 3 LDS.128 per 32 FFMA.
template <int F, int LAYER>
__global__ void k_gemm(const float* __restrict__ Xin, const float* __restrict__ W, int n) {
    constexpr int CG  = F / 8;          // column groups (8 cols each)
    constexpr int NG  = 256 / CG;       // node groups (4 nodes each)
    constexpr int NB  = NG * 4;         // nodes per block (64 or 128)
    constexpr int KC  = 32;             // k-chunk
    constexpr int NBP = NB + 4;         // padded row (16B-aligned stride)

    __shared__ __align__(16) float sW[KC][F];
    __shared__ __align__(16) float sX[KC][NBP];

    const float* __restrict__ in;
    float* __restrict__ out;
    if (LAYER == 1) { in = Xin;   out = g_Hs; }
    else            { in = g_h1;  out = g_Gs; }

    const int tid = threadIdx.x;
    const int cg  = tid % CG;
    const int ng  = tid / CG;
    const int node0 = blockIdx.x * NB;

    float acc[4][8];
    #pragma unroll
    for (int a = 0; a < 4; a++)
        #pragma unroll
        for (int b = 0; b < 8; b++) acc[a][b] = 0.f;

    for (int k0 = 0; k0 < DIN; k0 += KC) {
        // load W chunk (rows k0..k0+KC-1 contiguous in gmem)
        {
            const float4* wsrc = (const float4*)(W + (size_t)k0 * F);
            float4* wdst = (float4*)&sW[0][0];
            #pragma unroll
            for (int i = tid; i < KC * F / 4; i += 256) wdst[i] = wsrc[i];
        }
        // load X chunk, store transposed: sX[k][r]
        #pragma unroll
        for (int i = tid; i < NB * KC / 4; i += 256) {
            int r = i / (KC / 4);
            int c = i % (KC / 4);
            int node = node0 + r;
            float4 v = make_float4(0.f, 0.f, 0.f, 0.f);
            if (node < n) v = *(const float4*)(in + (size_t)node * DIN + k0 + c * 4);
            sX[c * 4 + 0][r] = v.x;
            sX[c * 4 + 1][r] = v.y;
            sX[c * 4 + 2][r] = v.z;
            sX[c * 4 + 3][r] = v.w;
        }
        __syncthreads();

        #pragma unroll
        for (int k = 0; k < KC; k++) {
            const float4 wa = *(const float4*)&sW[k][cg * 8];
            const float4 wb = *(const float4*)&sW[k][cg * 8 + 4];
            const float4 xv = *(const float4*)&sX[k][ng * 4];
            acc[0][0] += xv.x * wa.x; acc[0][1] += xv.x * wa.y;
            acc[0][2] += xv.x * wa.z; acc[0][3] += xv.x * wa.w;
            acc[0][4] += xv.x * wb.x; acc[0][5] += xv.x * wb.y;
            acc[0][6] += xv.x * wb.z; acc[0][7] += xv.x * wb.w;
            acc[1][0] += xv.y * wa.x; acc[1][1] += xv.y * wa.y;
            acc[1][2] += xv.y * wa.z; acc[1][3] += xv.y * wa.w;
            acc[1][4] += xv.y * wb.x; acc[1][5] += xv.y * wb.y;
            acc[1][6] += xv.y * wb.z; acc[1][7] += xv.y * wb.w;
            acc[2][0] += xv.z * wa.x; acc[2][1] += xv.z * wa.y;
            acc[2][2] += xv.z * wa.z; acc[2][3] += xv.z * wa.w;
            acc[2][4] += xv.z * wb.x; acc[2][5] += xv.z * wb.y;
            acc[2][6] += xv.z * wb.z; acc[2][7] += xv.z * wb.w;
            acc[3][0] += xv.w * wa.x; acc[3][1] += xv.w * wa.y;
            acc[3][2] += xv.w * wa.z; acc[3][3] += xv.w * wa.w;
            acc[3][4] += xv.w * wb.x; acc[3][5] += xv.w * wb.y;
            acc[3][6] += xv.w * wb.z; acc[3][7] += xv.w * wb.w;
        }
        __syncthreads();
    }

    #pragma unroll
    for (int ni = 0; ni < 4; ni++) {
        int node = node0 + ng * 4 + ni;
        if (node < n) {
            float dv = g_dinv[node];
            float* o = out + (size_t)node * F + cg * 8;
            float4 o0 = make_float4(acc[ni][0] * dv, acc[ni][1] * dv, acc[ni][2] * dv, acc[ni][3] * dv);
            float4 o1 = make_float4(acc[ni][4] * dv, acc[ni][5] * dv, acc[ni][6] * dv, acc[ni][7] * dv);
            *(float4*)(o) = o0;
            *(float4*)(o + 4) = o1;
        }
    }
}

// ---------------- aggregation layer 1: h1 = relu(dinv*(gather + self) + b1) ----------------
// one warp per node, 32 lanes x float4 = 512B row
__global__ void k_agg1(const float* __restrict__ bias, int n) {
    const int w = (blockIdx.x * blockDim.x + threadIdx.x) >> 5;
    const int lane = threadIdx.x & 31;
    if (w >= n) return;

    const int beg = g_rowptr[w];
    const int end = g_rowptr[w + 1];
    const float dv = g_dinv[w];

    const float4* __restrict__ H4 = (const float4*)g_Hs;
    float4 a = H4[(size_t)w * 32 + lane];   // self-loop term
    int e = beg;
    for (; e + 3 < end; e += 4) {
        int s0 = g_srcs[e], s1 = g_srcs[e + 1], s2 = g_srcs[e + 2], s3 = g_srcs[e + 3];
        float4 v0 = H4[(size_t)s0 * 32 + lane];
        float4 v1 = H4[(size_t)s1 * 32 + lane];
        float4 v2 = H4[(size_t)s2 * 32 + lane];
        float4 v3 = H4[(size_t)s3 * 32 + lane];
        a.x += v0.x + v1.x + v2.x + v3.x;
        a.y += v0.y + v1.y + v2.y + v3.y;
        a.z += v0.z + v1.z + v2.z + v3.z;
        a.w += v0.w + v1.w + v2.w + v3.w;
    }
    for (; e < end; e++) {
        int s = g_srcs[e];
        float4 v = H4[(size_t)s * 32 + lane];
        a.x += v.x; a.y += v.y; a.z += v.z; a.w += v.w;
    }
    float4 bb = ((const float4*)bias)[lane];
    float4 o;
    o.x = fmaxf(a.x * dv + bb.x, 0.f);
    o.y = fmaxf(a.y * dv + bb.y, 0.f);
    o.z = fmaxf(a.z * dv + bb.z, 0.f);
    o.w = fmaxf(a.w * dv + bb.w, 0.f);
    ((float4*)g_h1)[(size_t)w * 32 + lane] = o;
}

// ---------------- aggregation layer 2: out = dinv*(gather + self) + b2 ----------------
// HALF-warp per node: 16 lanes x float4 = 64-float row. 2 nodes/warp -> 2x issue parallelism.
__global__ void k_agg2(const float* __restrict__ bias, float* __restrict__ Yout, int n) {
    const int hw = (blockIdx.x * blockDim.x + threadIdx.x) >> 4;  // half-warp id = node
    const int l  = threadIdx.x & 15;
    if (hw >= n) return;

    const int beg = g_rowptr[hw];
    const int end = g_rowptr[hw + 1];
    const float dv = g_dinv[hw];

    const float4* __restrict__ G4 = (const float4*)g_Gs;
    float4 a = G4[(size_t)hw * 16 + l];   // self-loop term
    int e = beg;
    for (; e + 3 < end; e += 4) {
        int s0 = g_srcs[e], s1 = g_srcs[e + 1], s2 = g_srcs[e + 2], s3 = g_srcs[e + 3];
        float4 v0 = G4[(size_t)s0 * 16 + l];
        float4 v1 = G4[(size_t)s1 * 16 + l];
        float4 v2 = G4[(size_t)s2 * 16 + l];
        float4 v3 = G4[(size_t)s3 * 16 + l];
        a.x += v0.x + v1.x + v2.x + v3.x;
        a.y += v0.y + v1.y + v2.y + v3.y;
        a.z += v0.z + v1.z + v2.z + v3.z;
        a.w += v0.w + v1.w + v2.w + v3.w;
    }
    for (; e < end; e++) {
        int s = g_srcs[e];
        float4 v = G4[(size_t)s * 16 + l];
        a.x += v.x; a.y += v.y; a.z += v.z; a.w += v.w;
    }
    float4 bb = ((const float4*)bias)[l];
    float4 o;
    o.x = a.x * dv + bb.x;
    o.y = a.y * dv + bb.y;
    o.z = a.z * dv + bb.z;
    o.w = a.w * dv + bb.w;
    ((float4*)Yout)[(size_t)hw * 16 + l] = o;
}

// ---------------- launch ----------------
extern "C" void kernel_launch(void* const* d_in, const int* in_sizes, int n_in,
                              void* d_out, int out_size) {
    const float* x  = (const float*)d_in[0];
    const int*   ei = (const int*)d_in[1];    // int32 (JAX x64 disabled)
    const float* W1 = (const float*)d_in[2];
    const float* b1 = (const float*)d_in[3];
    const float* W2 = (const float*)d_in[4];
    const float* b2 = (const float*)d_in[5];
    float*       out = (float*)d_out;

    const int n = in_sizes[0] / 128;   // 50000
    const int E = in_sizes[1] / 2;     // 500000
    const int nb = (n + 511) / 512;    // 98 <= 128

    k_init<<<(n + 255) / 256, 256>>>(n);
    k_count<<<(E + 255) / 256, 256>>>(ei, E, n);
    k_scan1<<<nb, 512>>>(n);
    k_scan2<<<1, 128>>>(nb);
    k_scan3<<<(n + 255) / 256, 256>>>(n);
    k_fill<<<(E + 255) / 256, 256>>>(ei, E, n);

    // layer 1: Hs = (x@W1)*dinv ; h1 = relu(dinv*(gather + self) + b1)
    k_gemm<128, 1><<<(n + 63) / 64, 256>>>(x, W1, n);
    k_agg1<<<(n + 7) / 8, 256>>>(b1, n);

    // layer 2: Gs = (h1@W2)*dinv ; out = dinv*(gather + self) + b2
    k_gemm<64, 2><<<(n + 127) / 128, 256>>>(nullptr, W2, n);
    k_agg2<<<(n + 15) / 16, 256>>>(b2, out, n);
}

// round 12
// speedup vs baseline: 1.1560x; 1.1545x over previous
#include <cuda_runtime.h>
#include <cuda_bf16.h>
#include <stdint.h>

// Problem constants (fixed by the dataset)
#define MAXN 50000
#define MAXE 500000
#define DIN  128

// ---------------- scratch (device globals; no allocation allowed) ----------------
__device__ __align__(16) float g_Hs[(size_t)MAXN * 128];   // (X@W1)*dinv
__device__ __align__(16) float g_h1[(size_t)MAXN * 128];   // relu(layer1 out)
__device__ __align__(16) float g_Gs[(size_t)MAXN * 64];    // (h1@W2)*dinv
__device__ int   g_cnt[MAXN];                // in-degree (no self loop)
__device__ int   g_fill[MAXN];               // bucket fill cursors
__device__ int   g_rowptr[MAXN + 1];         // CSR row pointers (by dst)
__device__ int   g_srcs[MAXE];               // CSR column (src) indices
__device__ float g_dinv[MAXN];               // 1/sqrt(deg), deg = indeg+1
__device__ int   g_bsum[128];                // scan block sums

// ---------------- preprocessing ----------------
__global__ void k_init(int n) {
    int i = blockIdx.x * blockDim.x + threadIdx.x;
    if (i < n) { g_cnt[i] = 0; g_fill[i] = 0; }
}

// edge_index is int32 (JAX x64 disabled)
__global__ void k_count(const int* __restrict__ ei, int E, int n) {
    int e = blockIdx.x * blockDim.x + threadIdx.x;
    if (e < E) {
        int d = ei[E + e];
        if ((unsigned)d < (unsigned)n)
            atomicAdd(&g_cnt[d], 1);
    }
}

// exclusive scan, 512 elements per block; block sums to g_bsum
__global__ void k_scan1(int n) {
    __shared__ int sh[512];
    int i = blockIdx.x * 512 + threadIdx.x;
    int v = (i < n) ? g_cnt[i] : 0;
    sh[threadIdx.x] = v;
    __syncthreads();
    for (int off = 1; off < 512; off <<= 1) {
        int t = 0;
        if ((int)threadIdx.x >= off) t = sh[threadIdx.x - off];
        __syncthreads();
        sh[threadIdx.x] += t;
        __syncthreads();
    }
    int incl = sh[threadIdx.x];
    if (i < n) g_rowptr[i] = incl - v;       // block-local exclusive
    if (threadIdx.x == 511) g_bsum[blockIdx.x] = incl;
}

// fused: per-block redundant reduction of bsum[0..bid-1] (<=98 elems),
// then finalize rowptr + dinv. Replaces the separate k_scan2 launch.
__global__ void k_scan3f(int n) {
    __shared__ int sh[16];
    const int bid = blockIdx.x;
    const int t = threadIdx.x;

    int p = (t < bid) ? g_bsum[t] : 0;       // bid <= 97 < 512
    #pragma unroll
    for (int o = 16; o; o >>= 1) p += __shfl_down_sync(0xFFFFFFFFu, p, o);
    if ((t & 31) == 0) sh[t >> 5] = p;
    __syncthreads();
    if (t < 32) {
        int v = (t < 16) ? sh[t] : 0;
        #pragma unroll
        for (int o = 8; o; o >>= 1) v += __shfl_down_sync(0xFFFFFFFFu, v, o);
        if (t == 0) sh[0] = v;
    }
    __syncthreads();
    const int boff = sh[0];

    int i = bid * 512 + t;
    if (i < n) {
        int rp = g_rowptr[i] + boff;
        g_rowptr[i] = rp;
        g_dinv[i] = rsqrtf((float)(g_cnt[i] + 1));
        if (i == n - 1) g_rowptr[n] = rp + g_cnt[i];
    }
}

__global__ void k_fill(const int* __restrict__ ei, int E, int n) {
    int e = blockIdx.x * blockDim.x + threadIdx.x;
    if (e < E) {
        int s = ei[e];
        int d = ei[E + e];
        if ((unsigned)s < (unsigned)n && (unsigned)d < (unsigned)n) {
            int pos = g_rowptr[d] + atomicAdd(&g_fill[d], 1);
            g_srcs[pos] = s;
        }
    }
}

// ---------------- GEMM: out[node][f] = (sum_k in[node][k] * W[k][f]) * dinv[node] ----------------
// 8 nodes x 8 cols per thread: 64 FFMA per 4 LDS.128 -> fma-pipe-bound
// (per-k per-SM: 256 FFMA-issue cyc vs ~192 smem cyc).
template <int F, int LAYER>
__global__ void __launch_bounds__(256, 2) k_gemm(const float* __restrict__ Xin,
                                                 const float* __restrict__ W, int n) {
    constexpr int CG  = F / 8;          // column groups (8 cols each)
    constexpr int NG  = 256 / CG;       // node groups
    constexpr int NPT = 8;              // nodes per thread
    constexpr int NB  = NG * NPT;       // nodes per block (128 or 256)
    constexpr int KC  = 32;             // k-chunk
    constexpr int NBP = NB + 4;         // padded row stride (16B-aligned)

    __shared__ __align__(16) float sW[KC][F];
    __shared__ __align__(16) float sX[KC][NBP];

    const float* __restrict__ in;
    float* __restrict__ out;
    if (LAYER == 1) { in = Xin;   out = g_Hs; }
    else            { in = g_h1;  out = g_Gs; }

    const int tid = threadIdx.x;
    const int cg  = tid % CG;
    const int ng  = tid / CG;
    const int node0 = blockIdx.x * NB;

    float acc[NPT][8];
    #pragma unroll
    for (int a = 0; a < NPT; a++)
        #pragma unroll
        for (int b = 0; b < 8; b++) acc[a][b] = 0.f;

    for (int k0 = 0; k0 < DIN; k0 += KC) {
        // load W chunk (rows k0..k0+KC-1 contiguous in gmem)
        {
            const float4* wsrc = (const float4*)(W + (size_t)k0 * F);
            float4* wdst = (float4*)&sW[0][0];
            #pragma unroll
            for (int i = tid; i < KC * F / 4; i += 256) wdst[i] = wsrc[i];
        }
        // load X chunk, store transposed: sX[k][r]
        #pragma unroll
        for (int i = tid; i < NB * KC / 4; i += 256) {
            int r = i / (KC / 4);
            int c = i % (KC / 4);
            int node = node0 + r;
            float4 v = make_float4(0.f, 0.f, 0.f, 0.f);
            if (node < n) v = *(const float4*)(in + (size_t)node * DIN + k0 + c * 4);
            sX[c * 4 + 0][r] = v.x;
            sX[c * 4 + 1][r] = v.y;
            sX[c * 4 + 2][r] = v.z;
            sX[c * 4 + 3][r] = v.w;
        }
        __syncthreads();

        #pragma unroll
        for (int k = 0; k < KC; k++) {
            const float4 wa  = *(const float4*)&sW[k][cg * 8];
            const float4 wb  = *(const float4*)&sW[k][cg * 8 + 4];
            const float4 xv0 = *(const float4*)&sX[k][ng * NPT];
            const float4 xv1 = *(const float4*)&sX[k][ng * NPT + 4];
            const float xs[8] = { xv0.x, xv0.y, xv0.z, xv0.w, xv1.x, xv1.y, xv1.z, xv1.w };
            #pragma unroll
            for (int ni = 0; ni < NPT; ni++) {
                const float xv = xs[ni];
                acc[ni][0] += xv * wa.x; acc[ni][1] += xv * wa.y;
                acc[ni][2] += xv * wa.z; acc[ni][3] += xv * wa.w;
                acc[ni][4] += xv * wb.x; acc[ni][5] += xv * wb.y;
                acc[ni][6] += xv * wb.z; acc[ni][7] += xv * wb.w;
            }
        }
        __syncthreads();
    }

    #pragma unroll
    for (int ni = 0; ni < NPT; ni++) {
        int node = node0 + ng * NPT + ni;
        if (node < n) {
            float dv = g_dinv[node];
            float* o = out + (size_t)node * F + cg * 8;
            float4 o0 = make_float4(acc[ni][0] * dv, acc[ni][1] * dv, acc[ni][2] * dv, acc[ni][3] * dv);
            float4 o1 = make_float4(acc[ni][4] * dv, acc[ni][5] * dv, acc[ni][6] * dv, acc[ni][7] * dv);
            *(float4*)(o) = o0;
            *(float4*)(o + 4) = o1;
        }
    }
}

// ---------------- aggregation layer 1: h1 = relu(dinv*(gather + self) + b1) ----------------
// one warp per node, 32 lanes x float4 = 512B row
__global__ void k_agg1(const float* __restrict__ bias, int n) {
    const int w = (blockIdx.x * blockDim.x + threadIdx.x) >> 5;
    const int lane = threadIdx.x & 31;
    if (w >= n) return;

    const int beg = g_rowptr[w];
    const int end = g_rowptr[w + 1];
    const float dv = g_dinv[w];

    const float4* __restrict__ H4 = (const float4*)g_Hs;
    float4 a = H4[(size_t)w * 32 + lane];   // self-loop term
    int e = beg;
    for (; e + 3 < end; e += 4) {
        int s0 = g_srcs[e], s1 = g_srcs[e + 1], s2 = g_srcs[e + 2], s3 = g_srcs[e + 3];
        float4 v0 = H4[(size_t)s0 * 32 + lane];
        float4 v1 = H4[(size_t)s1 * 32 + lane];
        float4 v2 = H4[(size_t)s2 * 32 + lane];
        float4 v3 = H4[(size_t)s3 * 32 + lane];
        a.x += v0.x + v1.x + v2.x + v3.x;
        a.y += v0.y + v1.y + v2.y + v3.y;
        a.z += v0.z + v1.z + v2.z + v3.z;
        a.w += v0.w + v1.w + v2.w + v3.w;
    }
    for (; e < end; e++) {
        int s = g_srcs[e];
        float4 v = H4[(size_t)s * 32 + lane];
        a.x += v.x; a.y += v.y; a.z += v.z; a.w += v.w;
    }
    float4 bb = ((const float4*)bias)[lane];
    float4 o;
    o.x = fmaxf(a.x * dv + bb.x, 0.f);
    o.y = fmaxf(a.y * dv + bb.y, 0.f);
    o.z = fmaxf(a.z * dv + bb.z, 0.f);
    o.w = fmaxf(a.w * dv + bb.w, 0.f);
    ((float4*)g_h1)[(size_t)w * 32 + lane] = o;
}

// ---------------- aggregation layer 2: out = dinv*(gather + self) + b2 ----------------
// half-warp per node: 16 lanes x float4 = 64-float row
__global__ void k_agg2(const float* __restrict__ bias, float* __restrict__ Yout, int n) {
    const int hw = (blockIdx.x * blockDim.x + threadIdx.x) >> 4;
    const int l  = threadIdx.x & 15;
    if (hw >= n) return;

    const int beg = g_rowptr[hw];
    const int end = g_rowptr[hw + 1];
    const float dv = g_dinv[hw];

    const float4* __restrict__ G4 = (const float4*)g_Gs;
    float4 a = G4[(size_t)hw * 16 + l];   // self-loop term
    int e = beg;
    for (; e + 3 < end; e += 4) {
        int s0 = g_srcs[e], s1 = g_srcs[e + 1], s2 = g_srcs[e + 2], s3 = g_srcs[e + 3];
        float4 v0 = G4[(size_t)s0 * 16 + l];
        float4 v1 = G4[(size_t)s1 * 16 + l];
        float4 v2 = G4[(size_t)s2 * 16 + l];
        float4 v3 = G4[(size_t)s3 * 16 + l];
        a.x += v0.x + v1.x + v2.x + v3.x;
        a.y += v0.y + v1.y + v2.y + v3.y;
        a.z += v0.z + v1.z + v2.z + v3.z;
        a.w += v0.w + v1.w + v2.w + v3.w;
    }
    for (; e < end; e++) {
        int s = g_srcs[e];
        float4 v = G4[(size_t)s * 16 + l];
        a.x += v.x; a.y += v.y; a.z += v.z; a.w += v.w;
    }
    float4 bb = ((const float4*)bias)[l];
    float4 o;
    o.x = a.x * dv + bb.x;
    o.y = a.y * dv + bb.y;
    o.z = a.z * dv + bb.z;
    o.w = a.w * dv + bb.w;
    ((float4*)Yout)[(size_t)hw * 16 + l] = o;
}

// ---------------- launch ----------------
extern "C" void kernel_launch(void* const* d_in, const int* in_sizes, int n_in,
                              void* d_out, int out_size) {
    const float* x  = (const float*)d_in[0];
    const int*   ei = (const int*)d_in[1];    // int32 (JAX x64 disabled)
    const float* W1 = (const float*)d_in[2];
    const float* b1 = (const float*)d_in[3];
    const float* W2 = (const float*)d_in[4];
    const float* b2 = (const float*)d_in[5];
    float*       out = (float*)d_out;

    const int n = in_sizes[0] / 128;   // 50000
    const int E = in_sizes[1] / 2;     // 500000
    const int nb = (n + 511) / 512;    // 98

    k_init<<<(n + 255) / 256, 256>>>(n);            // launch 0
    k_count<<<(E + 255) / 256, 256>>>(ei, E, n);    // launch 1
    k_scan1<<<nb, 512>>>(n);                        // launch 2
    k_scan3f<<<nb, 512>>>(n);                       // launch 3 (scan2 fused in)
    k_fill<<<(E + 255) / 256, 256>>>(ei, E, n);     // launch 4

    // layer 1 (launch 5 = gemm1 -> lands under ncu -s 5)
    k_gemm<128, 1><<<(n + 127) / 128, 256>>>(x, W1, n);
    k_agg1<<<(n + 7) / 8, 256>>>(b1, n);

    // layer 2
    k_gemm<64, 2><<<(n + 255) / 256, 256>>>(nullptr, W2, n);
    k_agg2<<<(n + 15) / 16, 256>>>(b2, out, n);
}

// round 13
// speedup vs baseline: 1.2918x; 1.1175x over previous
#include <cuda_runtime.h>
#include <cuda_bf16.h>
#include <stdint.h>

// Problem constants (fixed by the dataset)
#define MAXN 50000
#define MAXE 500000
#define DIN  128

// packed fp32x2 FMA (sm_103a): d = a*b + d, elementwise on 2 packed fp32 lanes.
// ptxas never auto-generates FFMA2; PTX-only -> 2x fp32 FMA throughput.
#define FMA2(d, a, b) asm("fma.rn.f32x2 %0, %1, %2, %0;" : "+l"(d) : "l"(a), "l"(b))
#define DUP2(out, w)  asm("mov.b64 %0, {%1, %1};" : "=l"(out) : "r"(w))

// ---------------- scratch (device globals; no allocation allowed) ----------------
__device__ __align__(16) float g_Hs[(size_t)MAXN * 128];   // (X@W1)*dinv
__device__ __align__(16) float g_h1[(size_t)MAXN * 128];   // relu(layer1 out)
__device__ __align__(16) float g_Gs[(size_t)MAXN * 64];    // (h1@W2)*dinv
__device__ int   g_cnt[MAXN];                // in-degree (no self loop)
__device__ int   g_fill[MAXN];               // bucket fill cursors
__device__ int   g_rowptr[MAXN + 1];         // CSR row pointers (by dst)
__device__ int   g_srcs[MAXE];               // CSR column (src) indices
__device__ float g_dinv[MAXN];               // 1/sqrt(deg), deg = indeg+1
__device__ int   g_bsum[128];                // scan block sums

// ---------------- preprocessing ----------------
__global__ void k_init(int n) {
    int i = blockIdx.x * blockDim.x + threadIdx.x;
    if (i < n) { g_cnt[i] = 0; g_fill[i] = 0; }
}

// edge_index is int32 (JAX x64 disabled)
__global__ void k_count(const int* __restrict__ ei, int E, int n) {
    int e = blockIdx.x * blockDim.x + threadIdx.x;
    if (e < E) {
        int d = ei[E + e];
        if ((unsigned)d < (unsigned)n)
            atomicAdd(&g_cnt[d], 1);
    }
}

// exclusive scan, 512 elements per block; block sums to g_bsum
__global__ void k_scan1(int n) {
    __shared__ int sh[512];
    int i = blockIdx.x * 512 + threadIdx.x;
    int v = (i < n) ? g_cnt[i] : 0;
    sh[threadIdx.x] = v;
    __syncthreads();
    for (int off = 1; off < 512; off <<= 1) {
        int t = 0;
        if ((int)threadIdx.x >= off) t = sh[threadIdx.x - off];
        __syncthreads();
        sh[threadIdx.x] += t;
        __syncthreads();
    }
    int incl = sh[threadIdx.x];
    if (i < n) g_rowptr[i] = incl - v;       // block-local exclusive
    if (threadIdx.x == 511) g_bsum[blockIdx.x] = incl;
}

// fused: per-block redundant reduction of bsum[0..bid-1] (<=98 elems),
// then finalize rowptr + dinv.
__global__ void k_scan3f(int n) {
    __shared__ int sh[16];
    const int bid = blockIdx.x;
    const int t = threadIdx.x;

    int p = (t < bid) ? g_bsum[t] : 0;       // bid <= 97 < 512
    #pragma unroll
    for (int o = 16; o; o >>= 1) p += __shfl_down_sync(0xFFFFFFFFu, p, o);
    if ((t & 31) == 0) sh[t >> 5] = p;
    __syncthreads();
    if (t < 32) {
        int v = (t < 16) ? sh[t] : 0;
        #pragma unroll
        for (int o = 8; o; o >>= 1) v += __shfl_down_sync(0xFFFFFFFFu, v, o);
        if (t == 0) sh[0] = v;
    }
    __syncthreads();
    const int boff = sh[0];

    int i = bid * 512 + t;
    if (i < n) {
        int rp = g_rowptr[i] + boff;
        g_rowptr[i] = rp;
        g_dinv[i] = rsqrtf((float)(g_cnt[i] + 1));
        if (i == n - 1) g_rowptr[n] = rp + g_cnt[i];
    }
}

__global__ void k_fill(const int* __restrict__ ei, int E, int n) {
    int e = blockIdx.x * blockDim.x + threadIdx.x;
    if (e < E) {
        int s = ei[e];
        int d = ei[E + e];
        if ((unsigned)s < (unsigned)n && (unsigned)d < (unsigned)n) {
            int pos = g_rowptr[d] + atomicAdd(&g_fill[d], 1);
            g_srcs[pos] = s;
        }
    }
}

// ---------------- GEMM: out[node][f] = (sum_k in[node][k] * W[k][f]) * dinv[node] ----------------
// Accumulators packed over NODE PAIRS (adjacent in transposed sX tile) using
// fma.rn.f32x2: per k per thread 32 FFMA2 (+8 MOV64 + 4 LDS.128) instead of
// 64 FFMA -> fma-pipe issue per SM per k drops 256 -> ~128 cyc.
template <int F, int LAYER>
__global__ void __launch_bounds__(256, 2) k_gemm(const float* __restrict__ Xin,
                                                 const float* __restrict__ W, int n) {
    constexpr int CG  = F / 8;          // column groups (8 cols each)
    constexpr int NG  = 256 / CG;       // node groups
    constexpr int NPT = 8;              // nodes per thread (4 packed pairs)
    constexpr int NB  = NG * NPT;       // nodes per block (128 or 256)
    constexpr int KC  = 32;             // k-chunk
    constexpr int NBP = NB + 4;         // padded row stride (16B-aligned)

    __shared__ __align__(16) float sW[KC][F];
    __shared__ __align__(16) float sX[KC][NBP];

    const float* __restrict__ in;
    float* __restrict__ out;
    if (LAYER == 1) { in = Xin;   out = g_Hs; }
    else            { in = g_h1;  out = g_Gs; }

    const int tid = threadIdx.x;
    const int cg  = tid % CG;
    const int ng  = tid / CG;
    const int node0 = blockIdx.x * NB;

    // acc[p][c]: packed pair (node 2p, node 2p+1) x column cg*8+c
    unsigned long long acc[4][8];
    #pragma unroll
    for (int p = 0; p < 4; p++)
        #pragma unroll
        for (int c = 0; c < 8; c++) acc[p][c] = 0ull;

    for (int k0 = 0; k0 < DIN; k0 += KC) {
        // load W chunk (rows k0..k0+KC-1 contiguous in gmem)
        {
            const float4* wsrc = (const float4*)(W + (size_t)k0 * F);
            float4* wdst = (float4*)&sW[0][0];
            #pragma unroll
            for (int i = tid; i < KC * F / 4; i += 256) wdst[i] = wsrc[i];
        }
        // load X chunk, store transposed: sX[k][r]
        #pragma unroll
        for (int i = tid; i < NB * KC / 4; i += 256) {
            int r = i / (KC / 4);
            int c = i % (KC / 4);
            int node = node0 + r;
            float4 v = make_float4(0.f, 0.f, 0.f, 0.f);
            if (node < n) v = *(const float4*)(in + (size_t)node * DIN + k0 + c * 4);
            sX[c * 4 + 0][r] = v.x;
            sX[c * 4 + 1][r] = v.y;
            sX[c * 4 + 2][r] = v.z;
            sX[c * 4 + 3][r] = v.w;
        }
        __syncthreads();

        #pragma unroll
        for (int k = 0; k < KC; k++) {
            const float4 wa = *(const float4*)&sW[k][cg * 8];
            const float4 wb = *(const float4*)&sW[k][cg * 8 + 4];
            unsigned long long wd[8];
            DUP2(wd[0], __float_as_uint(wa.x)); DUP2(wd[1], __float_as_uint(wa.y));
            DUP2(wd[2], __float_as_uint(wa.z)); DUP2(wd[3], __float_as_uint(wa.w));
            DUP2(wd[4], __float_as_uint(wb.x)); DUP2(wd[5], __float_as_uint(wb.y));
            DUP2(wd[6], __float_as_uint(wb.z)); DUP2(wd[7], __float_as_uint(wb.w));
            const ulonglong2 xA = *(const ulonglong2*)&sX[k][ng * NPT];
            const ulonglong2 xB = *(const ulonglong2*)&sX[k][ng * NPT + 4];
            const unsigned long long xp[4] = { xA.x, xA.y, xB.x, xB.y };
            #pragma unroll
            for (int p = 0; p < 4; p++)
                #pragma unroll
                for (int c = 0; c < 8; c++)
                    FMA2(acc[p][c], xp[p], wd[c]);
        }
        __syncthreads();
    }

    #pragma unroll
    for (int p = 0; p < 4; p++) {
        float2 c0 = *(float2*)&acc[p][0], c1 = *(float2*)&acc[p][1];
        float2 c2 = *(float2*)&acc[p][2], c3 = *(float2*)&acc[p][3];
        float2 c4 = *(float2*)&acc[p][4], c5 = *(float2*)&acc[p][5];
        float2 c6 = *(float2*)&acc[p][6], c7 = *(float2*)&acc[p][7];
        int ne = node0 + ng * NPT + 2 * p;         // even node of the pair
        if (ne < n) {
            float dv = g_dinv[ne];
            float* o = out + (size_t)ne * F + cg * 8;
            *(float4*)(o)     = make_float4(c0.x * dv, c1.x * dv, c2.x * dv, c3.x * dv);
            *(float4*)(o + 4) = make_float4(c4.x * dv, c5.x * dv, c6.x * dv, c7.x * dv);
        }
        if (ne + 1 < n) {
            float dv = g_dinv[ne + 1];
            float* o = out + (size_t)(ne + 1) * F + cg * 8;
            *(float4*)(o)     = make_float4(c0.y * dv, c1.y * dv, c2.y * dv, c3.y * dv);
            *(float4*)(o + 4) = make_float4(c4.y * dv, c5.y * dv, c6.y * dv, c7.y * dv);
        }
    }
}

// ---------------- aggregation layer 1: h1 = relu(dinv*(gather + self) + b1) ----------------
// one warp per node, 32 lanes x float4 = 512B row
__global__ void k_agg1(const float* __restrict__ bias, int n) {
    const int w = (blockIdx.x * blockDim.x + threadIdx.x) >> 5;
    const int lane = threadIdx.x & 31;
    if (w >= n) return;

    const int beg = g_rowptr[w];
    const int end = g_rowptr[w + 1];
    const float dv = g_dinv[w];

    const float4* __restrict__ H4 = (const float4*)g_Hs;
    float4 a = H4[(size_t)w * 32 + lane];   // self-loop term
    int e = beg;
    for (; e + 3 < end; e += 4) {
        int s0 = g_srcs[e], s1 = g_srcs[e + 1], s2 = g_srcs[e + 2], s3 = g_srcs[e + 3];
        float4 v0 = H4[(size_t)s0 * 32 + lane];
        float4 v1 = H4[(size_t)s1 * 32 + lane];
        float4 v2 = H4[(size_t)s2 * 32 + lane];
        float4 v3 = H4[(size_t)s3 * 32 + lane];
        a.x += v0.x + v1.x + v2.x + v3.x;
        a.y += v0.y + v1.y + v2.y + v3.y;
        a.z += v0.z + v1.z + v2.z + v3.z;
        a.w += v0.w + v1.w + v2.w + v3.w;
    }
    for (; e < end; e++) {
        int s = g_srcs[e];
        float4 v = H4[(size_t)s * 32 + lane];
        a.x += v.x; a.y += v.y; a.z += v.z; a.w += v.w;
    }
    float4 bb = ((const float4*)bias)[lane];
    float4 o;
    o.x = fmaxf(a.x * dv + bb.x, 0.f);
    o.y = fmaxf(a.y * dv + bb.y, 0.f);
    o.z = fmaxf(a.z * dv + bb.z, 0.f);
    o.w = fmaxf(a.w * dv + bb.w, 0.f);
    ((float4*)g_h1)[(size_t)w * 32 + lane] = o;
}

// ---------------- aggregation layer 2: out = dinv*(gather + self) + b2 ----------------
// half-warp per node: 16 lanes x float4 = 64-float row
__global__ void k_agg2(const float* __restrict__ bias, float* __restrict__ Yout, int n) {
    const int hw = (blockIdx.x * blockDim.x + threadIdx.x) >> 4;
    const int l  = threadIdx.x & 15;
    if (hw >= n) return;

    const int beg = g_rowptr[hw];
    const int end = g_rowptr[hw + 1];
    const float dv = g_dinv[hw];

    const float4* __restrict__ G4 = (const float4*)g_Gs;
    float4 a = G4[(size_t)hw * 16 + l];   // self-loop term
    int e = beg;
    for (; e + 3 < end; e += 4) {
        int s0 = g_srcs[e], s1 = g_srcs[e + 1], s2 = g_srcs[e + 2], s3 = g_srcs[e + 3];
        float4 v0 = G4[(size_t)s0 * 16 + l];
        float4 v1 = G4[(size_t)s1 * 16 + l];
        float4 v2 = G4[(size_t)s2 * 16 + l];
        float4 v3 = G4[(size_t)s3 * 16 + l];
        a.x += v0.x + v1.x + v2.x + v3.x;
        a.y += v0.y + v1.y + v2.y + v3.y;
        a.z += v0.z + v1.z + v2.z + v3.z;
        a.w += v0.w + v1.w + v2.w + v3.w;
    }
    for (; e < end; e++) {
        int s = g_srcs[e];
        float4 v = G4[(size_t)s * 16 + l];
        a.x += v.x; a.y += v.y; a.z += v.z; a.w += v.w;
    }
    float4 bb = ((const float4*)bias)[l];
    float4 o;
    o.x = a.x * dv + bb.x;
    o.y = a.y * dv + bb.y;
    o.z = a.z * dv + bb.z;
    o.w = a.w * dv + bb.w;
    ((float4*)Yout)[(size_t)hw * 16 + l] = o;
}

// ---------------- launch ----------------
extern "C" void kernel_launch(void* const* d_in, const int* in_sizes, int n_in,
                              void* d_out, int out_size) {
    const float* x  = (const float*)d_in[0];
    const int*   ei = (const int*)d_in[1];    // int32 (JAX x64 disabled)
    const float* W1 = (const float*)d_in[2];
    const float* b1 = (const float*)d_in[3];
    const float* W2 = (const float*)d_in[4];
    const float* b2 = (const float*)d_in[5];
    float*       out = (float*)d_out;

    const int n = in_sizes[0] / 128;   // 50000
    const int E = in_sizes[1] / 2;     // 500000
    const int nb = (n + 511) / 512;    // 98

    k_init<<<(n + 255) / 256, 256>>>(n);
    k_count<<<(E + 255) / 256, 256>>>(ei, E, n);
    k_scan1<<<nb, 512>>>(n);
    k_scan3f<<<nb, 512>>>(n);
    k_fill<<<(E + 255) / 256, 256>>>(ei, E, n);

    // layer 1: Hs = (x@W1)*dinv ; h1 = relu(dinv*(gather + self) + b1)
    k_gemm<128, 1><<<(n + 127) / 128, 256>>>(x, W1, n);
    k_agg1<<<(n + 7) / 8, 256>>>(b1, n);

    // layer 2: Gs = (h1@W2)*dinv ; out = dinv*(gather + self) + b2
    k_gemm<64, 2><<<(n + 255) / 256, 256>>>(nullptr, W2, n);
    k_agg2<<<(n + 15) / 16, 256>>>(b2, out, n);
}

// round 14
// speedup vs baseline: 1.3771x; 1.0660x over previous
#include <cuda_runtime.h>
#include <cuda_bf16.h>
#include <stdint.h>

// Problem constants (fixed by the dataset)
#define MAXN 50000
#define MAXE 500000
#define DIN  128

// packed fp32x2 FMA (sm_103a): d = a*b + d, elementwise on 2 packed fp32 lanes.
// ptxas never auto-generates FFMA2; PTX-only -> 2x fp32 FMA throughput.
#define FMA2(d, a, b) asm("fma.rn.f32x2 %0, %1, %2, %0;" : "+l"(d) : "l"(a), "l"(b))
#define DUP2(out, w)  asm("mov.b64 %0, {%1, %1};" : "=l"(out) : "r"(w))

// ---------------- scratch (device globals; no allocation allowed) ----------------
__device__ __align__(16) float g_Hs[(size_t)MAXN * 128];   // X@W1 (UNSCALED)
__device__ __align__(16) float g_h1[(size_t)MAXN * 128];   // relu(layer1 out)
__device__ __align__(16) float g_Gs[(size_t)MAXN * 64];    // (h1@W2)*dinv
__device__ int   g_cnt[MAXN];                // in-degree (no self loop)
__device__ int   g_fill[MAXN];               // bucket fill cursors
__device__ int   g_rowptr[MAXN + 1];         // CSR row pointers (by dst)
__device__ int   g_srcs[MAXE];               // CSR column (src) indices
__device__ float g_dinv[MAXN];               // 1/sqrt(deg), deg = indeg+1
__device__ int   g_bsum[128];                // scan block sums

// ---------------- preprocessing ----------------
// edge_index is int32 (JAX x64 disabled)
__global__ void k_count(const int* __restrict__ ei, int E, int n) {
    int e = blockIdx.x * blockDim.x + threadIdx.x;
    if (e < E) {
        int d = ei[E + e];
        if ((unsigned)d < (unsigned)n)
            atomicAdd(&g_cnt[d], 1);
    }
}

// exclusive scan, 512 elements per block; block sums to g_bsum
__global__ void k_scan1(int n) {
    __shared__ int sh[512];
    int i = blockIdx.x * 512 + threadIdx.x;
    int v = (i < n) ? g_cnt[i] : 0;
    sh[threadIdx.x] = v;
    __syncthreads();
    for (int off = 1; off < 512; off <<= 1) {
        int t = 0;
        if ((int)threadIdx.x >= off) t = sh[threadIdx.x - off];
        __syncthreads();
        sh[threadIdx.x] += t;
        __syncthreads();
    }
    int incl = sh[threadIdx.x];
    if (i < n) g_rowptr[i] = incl - v;       // block-local exclusive
    if (threadIdx.x == 511) g_bsum[blockIdx.x] = incl;
}

// fused: per-block redundant reduction of bsum[0..bid-1] (<=98 elems),
// then finalize rowptr + dinv.
__global__ void k_scan3f(int n) {
    __shared__ int sh[16];
    const int bid = blockIdx.x;
    const int t = threadIdx.x;

    int p = (t < bid) ? g_bsum[t] : 0;       // bid <= 97 < 512
    #pragma unroll
    for (int o = 16; o; o >>= 1) p += __shfl_down_sync(0xFFFFFFFFu, p, o);
    if ((t & 31) == 0) sh[t >> 5] = p;
    __syncthreads();
    if (t < 32) {
        int v = (t < 16) ? sh[t] : 0;
        #pragma unroll
        for (int o = 8; o; o >>= 1) v += __shfl_down_sync(0xFFFFFFFFu, v, o);
        if (t == 0) sh[0] = v;
    }
    __syncthreads();
    const int boff = sh[0];

    int i = bid * 512 + t;
    if (i < n) {
        int rp = g_rowptr[i] + boff;
        g_rowptr[i] = rp;
        g_dinv[i] = rsqrtf((float)(g_cnt[i] + 1));
        if (i == n - 1) g_rowptr[n] = rp + g_cnt[i];
    }
}

__global__ void k_fill(const int* __restrict__ ei, int E, int n) {
    int e = blockIdx.x * blockDim.x + threadIdx.x;
    if (e < E) {
        int s = ei[e];
        int d = ei[E + e];
        if ((unsigned)s < (unsigned)n && (unsigned)d < (unsigned)n) {
            int pos = g_rowptr[d] + atomicAdd(&g_fill[d], 1);
            g_srcs[pos] = s;
        }
    }
}

// ---------------- GEMM ----------------
// LAYER==1: out = Xin@W1, NO dinv scaling (so it can run concurrently with the
//           CSR/dinv build). LAYER==2: out = (g_h1@W2)*dinv.
// Node-pair-packed fma.rn.f32x2 accumulators: 32 FFMA2 per k per thread.
template <int F, int LAYER>
__global__ void __launch_bounds__(256, 2) k_gemm(const float* __restrict__ Xin,
                                                 const float* __restrict__ W, int n) {
    constexpr int CG  = F / 8;          // column groups (8 cols each)
    constexpr int NG  = 256 / CG;       // node groups
    constexpr int NPT = 8;              // nodes per thread (4 packed pairs)
    constexpr int NB  = NG * NPT;       // nodes per block (128 or 256)
    constexpr int KC  = 32;             // k-chunk
    constexpr int NBP = NB + 4;         // padded row stride (16B-aligned)

    __shared__ __align__(16) float sW[KC][F];
    __shared__ __align__(16) float sX[KC][NBP];

    const float* __restrict__ in;
    float* __restrict__ out;
    if (LAYER == 1) { in = Xin;   out = g_Hs; }
    else            { in = g_h1;  out = g_Gs; }

    const int tid = threadIdx.x;
    const int cg  = tid % CG;
    const int ng  = tid / CG;
    const int node0 = blockIdx.x * NB;

    unsigned long long acc[4][8];
    #pragma unroll
    for (int p = 0; p < 4; p++)
        #pragma unroll
        for (int c = 0; c < 8; c++) acc[p][c] = 0ull;

    for (int k0 = 0; k0 < DIN; k0 += KC) {
        {
            const float4* wsrc = (const float4*)(W + (size_t)k0 * F);
            float4* wdst = (float4*)&sW[0][0];
            #pragma unroll
            for (int i = tid; i < KC * F / 4; i += 256) wdst[i] = wsrc[i];
        }
        #pragma unroll
        for (int i = tid; i < NB * KC / 4; i += 256) {
            int r = i / (KC / 4);
            int c = i % (KC / 4);
            int node = node0 + r;
            float4 v = make_float4(0.f, 0.f, 0.f, 0.f);
            if (node < n) v = *(const float4*)(in + (size_t)node * DIN + k0 + c * 4);
            sX[c * 4 + 0][r] = v.x;
            sX[c * 4 + 1][r] = v.y;
            sX[c * 4 + 2][r] = v.z;
            sX[c * 4 + 3][r] = v.w;
        }
        __syncthreads();

        #pragma unroll
        for (int k = 0; k < KC; k++) {
            const float4 wa = *(const float4*)&sW[k][cg * 8];
            const float4 wb = *(const float4*)&sW[k][cg * 8 + 4];
            unsigned long long wd[8];
            DUP2(wd[0], __float_as_uint(wa.x)); DUP2(wd[1], __float_as_uint(wa.y));
            DUP2(wd[2], __float_as_uint(wa.z)); DUP2(wd[3], __float_as_uint(wa.w));
            DUP2(wd[4], __float_as_uint(wb.x)); DUP2(wd[5], __float_as_uint(wb.y));
            DUP2(wd[6], __float_as_uint(wb.z)); DUP2(wd[7], __float_as_uint(wb.w));
            const ulonglong2 xA = *(const ulonglong2*)&sX[k][ng * NPT];
            const ulonglong2 xB = *(const ulonglong2*)&sX[k][ng * NPT + 4];
            const unsigned long long xp[4] = { xA.x, xA.y, xB.x, xB.y };
            #pragma unroll
            for (int p = 0; p < 4; p++)
                #pragma unroll
                for (int c = 0; c < 8; c++)
                    FMA2(acc[p][c], xp[p], wd[c]);
        }
        __syncthreads();
    }

    #pragma unroll
    for (int p = 0; p < 4; p++) {
        float2 c0 = *(float2*)&acc[p][0], c1 = *(float2*)&acc[p][1];
        float2 c2 = *(float2*)&acc[p][2], c3 = *(float2*)&acc[p][3];
        float2 c4 = *(float2*)&acc[p][4], c5 = *(float2*)&acc[p][5];
        float2 c6 = *(float2*)&acc[p][6], c7 = *(float2*)&acc[p][7];
        int ne = node0 + ng * NPT + 2 * p;
        if (ne < n) {
            float dv = (LAYER == 2) ? g_dinv[ne] : 1.0f;
            float* o = out + (size_t)ne * F + cg * 8;
            *(float4*)(o)     = make_float4(c0.x * dv, c1.x * dv, c2.x * dv, c3.x * dv);
            *(float4*)(o + 4) = make_float4(c4.x * dv, c5.x * dv, c6.x * dv, c7.x * dv);
        }
        if (ne + 1 < n) {
            float dv = (LAYER == 2) ? g_dinv[ne + 1] : 1.0f;
            float* o = out + (size_t)(ne + 1) * F + cg * 8;
            *(float4*)(o)     = make_float4(c0.y * dv, c1.y * dv, c2.y * dv, c3.y * dv);
            *(float4*)(o + 4) = make_float4(c4.y * dv, c5.y * dv, c6.y * dv, c7.y * dv);
        }
    }
}

// ---------------- aggregation layer 1 ----------------
// Hs is UNSCALED: h1 = relu( dinv_i*( sum_e Hs[s]*dinv[s] + Hs[i]*dinv[i] ) + b1 )
// one warp per node, 32 lanes x float4 = 512B row; dinv[s] is a uniform
// broadcast scalar load per edge, folded via FMA.
__global__ void k_agg1(const float* __restrict__ bias, int n) {
    const int w = (blockIdx.x * blockDim.x + threadIdx.x) >> 5;
    const int lane = threadIdx.x & 31;
    if (w >= n) return;

    const int beg = g_rowptr[w];
    const int end = g_rowptr[w + 1];
    const float dv = g_dinv[w];

    const float4* __restrict__ H4 = (const float4*)g_Hs;
    float4 hs = H4[(size_t)w * 32 + lane];
    float4 a = make_float4(hs.x * dv, hs.y * dv, hs.z * dv, hs.w * dv); // self: Hs[i]*dinv[i]
    int e = beg;
    for (; e + 3 < end; e += 4) {
        int s0 = g_srcs[e], s1 = g_srcs[e + 1], s2 = g_srcs[e + 2], s3 = g_srcs[e + 3];
        float d0 = g_dinv[s0], d1 = g_dinv[s1], d2 = g_dinv[s2], d3 = g_dinv[s3];
        float4 v0 = H4[(size_t)s0 * 32 + lane];
        float4 v1 = H4[(size_t)s1 * 32 + lane];
        float4 v2 = H4[(size_t)s2 * 32 + lane];
        float4 v3 = H4[(size_t)s3 * 32 + lane];
        a.x = fmaf(v0.x, d0, a.x); a.y = fmaf(v0.y, d0, a.y);
        a.z = fmaf(v0.z, d0, a.z); a.w = fmaf(v0.w, d0, a.w);
        a.x = fmaf(v1.x, d1, a.x); a.y = fmaf(v1.y, d1, a.y);
        a.z = fmaf(v1.z, d1, a.z); a.w = fmaf(v1.w, d1, a.w);
        a.x = fmaf(v2.x, d2, a.x); a.y = fmaf(v2.y, d2, a.y);
        a.z = fmaf(v2.z, d2, a.z); a.w = fmaf(v2.w, d2, a.w);
        a.x = fmaf(v3.x, d3, a.x); a.y = fmaf(v3.y, d3, a.y);
        a.z = fmaf(v3.z, d3, a.z); a.w = fmaf(v3.w, d3, a.w);
    }
    for (; e < end; e++) {
        int s = g_srcs[e];
        float ds = g_dinv[s];
        float4 v = H4[(size_t)s * 32 + lane];
        a.x = fmaf(v.x, ds, a.x); a.y = fmaf(v.y, ds, a.y);
        a.z = fmaf(v.z, ds, a.z); a.w = fmaf(v.w, ds, a.w);
    }
    float4 bb = ((const float4*)bias)[lane];
    float4 o;
    o.x = fmaxf(a.x * dv + bb.x, 0.f);
    o.y = fmaxf(a.y * dv + bb.y, 0.f);
    o.z = fmaxf(a.z * dv + bb.z, 0.f);
    o.w = fmaxf(a.w * dv + bb.w, 0.f);
    ((float4*)g_h1)[(size_t)w * 32 + lane] = o;
}

// ---------------- aggregation layer 2: out = dinv*(gather + self) + b2 ----------------
// Gs is dinv-scaled already; half-warp per node: 16 lanes x float4 = 64-float row
__global__ void k_agg2(const float* __restrict__ bias, float* __restrict__ Yout, int n) {
    const int hw = (blockIdx.x * blockDim.x + threadIdx.x) >> 4;
    const int l  = threadIdx.x & 15;
    if (hw >= n) return;

    const int beg = g_rowptr[hw];
    const int end = g_rowptr[hw + 1];
    const float dv = g_dinv[hw];

    const float4* __restrict__ G4 = (const float4*)g_Gs;
    float4 a = G4[(size_t)hw * 16 + l];   // self-loop term
    int e = beg;
    for (; e + 3 < end; e += 4) {
        int s0 = g_srcs[e], s1 = g_srcs[e + 1], s2 = g_srcs[e + 2], s3 = g_srcs[e + 3];
        float4 v0 = G4[(size_t)s0 * 16 + l];
        float4 v1 = G4[(size_t)s1 * 16 + l];
        float4 v2 = G4[(size_t)s2 * 16 + l];
        float4 v3 = G4[(size_t)s3 * 16 + l];
        a.x += v0.x + v1.x + v2.x + v3.x;
        a.y += v0.y + v1.y + v2.y + v3.y;
        a.z += v0.z + v1.z + v2.z + v3.z;
        a.w += v0.w + v1.w + v2.w + v3.w;
    }
    for (; e < end; e++) {
        int s = g_srcs[e];
        float4 v = G4[(size_t)s * 16 + l];
        a.x += v.x; a.y += v.y; a.z += v.z; a.w += v.w;
    }
    float4 bb = ((const float4*)bias)[l];
    float4 o;
    o.x = a.x * dv + bb.x;
    o.y = a.y * dv + bb.y;
    o.z = a.z * dv + bb.z;
    o.w = a.w * dv + bb.w;
    ((float4*)Yout)[(size_t)hw * 16 + l] = o;
}

// ---------------- launch ----------------
extern "C" void kernel_launch(void* const* d_in, const int* in_sizes, int n_in,
                              void* d_out, int out_size) {
    const float* x  = (const float*)d_in[0];
    const int*   ei = (const int*)d_in[1];    // int32 (JAX x64 disabled)
    const float* W1 = (const float*)d_in[2];
    const float* b1 = (const float*)d_in[3];
    const float* W2 = (const float*)d_in[4];
    const float* b2 = (const float*)d_in[5];
    float*       out = (float*)d_out;

    const int n = in_sizes[0] / 128;   // 50000
    const int E = in_sizes[1] / 2;     // 500000
    const int nb = (n + 511) / 512;    // 98

    // One-time host resources (no device allocation; identical work every call).
    static cudaStream_t s2 = nullptr;
    static cudaEvent_t evFork = nullptr, evJoin = nullptr;
    static void *p_cnt = nullptr, *p_fill = nullptr;
    if (!s2) {
        cudaStreamCreateWithFlags(&s2, cudaStreamNonBlocking);
        cudaEventCreateWithFlags(&evFork, cudaEventDisableTiming);
        cudaEventCreateWithFlags(&evJoin, cudaEventDisableTiming);
        cudaGetSymbolAddress(&p_cnt, g_cnt);
        cudaGetSymbolAddress(&p_fill, g_fill);
    }

    // ---- fork: gemm1 (needs only x, W1) runs concurrent with the CSR build ----
    cudaEventRecord(evFork, 0);
    cudaStreamWaitEvent(s2, evFork, 0);
    k_gemm<128, 1><<<(n + 127) / 128, 256, 0, s2>>>(x, W1, n);
    cudaEventRecord(evJoin, s2);

    // ---- CSR build chain (stream 0) ----
    cudaMemsetAsync(p_cnt, 0, (size_t)n * sizeof(int), 0);
    cudaMemsetAsync(p_fill, 0, (size_t)n * sizeof(int), 0);
    k_count<<<(E + 255) / 256, 256>>>(ei, E, n);
    k_scan1<<<nb, 512>>>(n);
    k_scan3f<<<nb, 512>>>(n);
    k_fill<<<(E + 255) / 256, 256>>>(ei, E, n);

    // ---- join, then layer-1 aggregation ----
    cudaStreamWaitEvent(0, evJoin, 0);
    k_agg1<<<(n + 7) / 8, 256>>>(b1, n);

    // ---- layer 2 (serial chain) ----
    k_gemm<64, 2><<<(n + 255) / 256, 256>>>(nullptr, W2, n);
    k_agg2<<<(n + 15) / 16, 256>>>(b2, out, n);
}